// round 8
// baseline (speedup 1.0000x reference)
#include <cuda_runtime.h>
#include <math.h>
#include <string.h>

#define NFFT   4096
#define MH     2048            // half length
#define CIN    4
#define COUT   4
#define RANK   4
#define BATCH  32
#define NPART  CIN             // 4 partials per (j,b) after in-CTA s-accumulation
#define SMEMC  2176            // 2048 + 2048/16 padding (float2 slots)
#define P16(i) ((i) + ((i) >> 4))

#define TWO_PI 6.283185307179586476f
#define A1 ((float)(3.14159265358979323846 / 4096.0))   // e^{i*A1*m}
#define A2 ((float)(3.14159265358979323846 / 2048.0))   // e^{-i*A2*m}
#define INV_M (1.0f / 2048.0f)

// ---------------- device scratch (static; no runtime allocation) ------------
__device__ float2 d_Gf[CIN*COUT*RANK][MH];          // rfft(g) bins 0..2047
__device__ float  d_GfN[CIN*COUT*RANK];             // rfft(g) Nyquist bin (real)
__device__ float2 d_Hf[CIN*COUT*RANK][MH];          // folded negacyclic transform of h~
__device__ float2 d_Xf[CIN*BATCH][MH];              // folded negacyclic transform of x
__device__ float2 d_Yp[NPART][COUT*BATCH][MH];      // per-i partial spectra
__device__ float  d_YpN[NPART][COUT*BATCH];         // per-i partial Nyquist

// ---------------- complex helpers -------------------------------------------
__device__ __forceinline__ float2 cmul(float2 a, float2 b) {
    return make_float2(fmaf(a.x, b.x, -a.y*b.y), fmaf(a.x, b.y, a.y*b.x));
}
// packed f32x2 add/sub (sm_100+): one issue slot for both lanes
__device__ __forceinline__ float2 cadd(float2 a, float2 b) {
    unsigned long long au, bu, ru;
    memcpy(&au, &a, 8); memcpy(&bu, &b, 8);
    asm("add.rn.f32x2 %0, %1, %2;" : "=l"(ru) : "l"(au), "l"(bu));
    float2 r; memcpy(&r, &ru, 8); return r;
}
__device__ __forceinline__ float2 csub(float2 a, float2 b) {
    unsigned long long au, bu, ru;
    memcpy(&au, &a, 8); memcpy(&bu, &b, 8);
    asm("sub.rn.f32x2 %0, %1, %2;" : "=l"(ru) : "l"(au), "l"(bu));
    float2 r; memcpy(&r, &ru, 8); return r;
}

template<int SIGN>
__device__ __forceinline__ void b4(float2& a, float2& b, float2& c, float2& d) {
    float2 s0 = cadd(a, c), d0 = csub(a, c);
    float2 s1 = cadd(b, d), d1 = csub(b, d);
    a = cadd(s0, s1);
    c = csub(s0, s1);
    float2 nb, nd;
    if (SIGN < 0) {   // jd1 = (d1.y, -d1.x)
        nb = make_float2(d0.x + d1.y, d0.y - d1.x);
        nd = make_float2(d0.x - d1.y, d0.y + d1.x);
    } else {          // jd1 = (-d1.y, d1.x)
        nb = make_float2(d0.x - d1.y, d0.y + d1.x);
        nd = make_float2(d0.x + d1.y, d0.y - d1.x);
    }
    b = nb; d = nd;
}

template<int SIGN>
__device__ __forceinline__ float2 W16(float c, float s) {
    return make_float2(c, (SIGN < 0) ? -s : s);
}

// 16-pt DFT, natural order in/out, in registers.
template<int SIGN>
__device__ __forceinline__ void dft16(float2 u[16]) {
    const float C1 = 0.92387953251128674f;
    const float S1 = 0.38268343236508978f;
    const float HQ = 0.70710678118654752f;
    #pragma unroll
    for (int t = 0; t < 4; t++) b4<SIGN>(u[t], u[t+4], u[t+8], u[t+12]);
    float2 y[16];
    {
        float2 e0=u[0], e1=u[1], e2=u[2], e3=u[3];
        b4<SIGN>(e0,e1,e2,e3);
        y[0]=e0; y[4]=e1; y[8]=e2; y[12]=e3;
    }
    {
        float2 e0=u[4];
        float2 e1=cmul(u[5], W16<SIGN>(C1, S1));
        float2 e2=cmul(u[6], W16<SIGN>(HQ, HQ));
        float2 e3=cmul(u[7], W16<SIGN>(S1, C1));
        b4<SIGN>(e0,e1,e2,e3);
        y[1]=e0; y[5]=e1; y[9]=e2; y[13]=e3;
    }
    {
        float2 e0=u[8];
        float2 e1=cmul(u[9],  W16<SIGN>(HQ, HQ));
        float2 e2=cmul(u[10], W16<SIGN>(0.f, 1.f));
        float2 e3=cmul(u[11], W16<SIGN>(-HQ, HQ));
        b4<SIGN>(e0,e1,e2,e3);
        y[2]=e0; y[6]=e1; y[10]=e2; y[14]=e3;
    }
    {
        float2 e0=u[12];
        float2 e1=cmul(u[13], W16<SIGN>(S1, C1));
        float2 e2=cmul(u[14], W16<SIGN>(-HQ, HQ));
        float2 e3=cmul(u[15], W16<SIGN>(-C1, -S1));
        b4<SIGN>(e0,e1,e2,e3);
        y[3]=e0; y[7]=e1; y[11]=e2; y[15]=e3;
    }
    #pragma unroll
    for (int m = 0; m < 16; m++) u[m] = y[m];
}

// 8-pt DFT, natural order in/out.
template<int SIGN>
__device__ __forceinline__ void dft8(float2 u[8]) {
    const float HQ = 0.70710678118654752f;
    float2 e0=u[0], e1=u[2], e2=u[4], e3=u[6];
    float2 o0=u[1], o1=u[3], o2=u[5], o3=u[7];
    b4<SIGN>(e0,e1,e2,e3);
    b4<SIGN>(o0,o1,o2,o3);
    float2 t1 = cmul(o1, W16<SIGN>(HQ, HQ));
    float2 t2 = cmul(o2, W16<SIGN>(0.f, 1.f));
    float2 t3 = cmul(o3, W16<SIGN>(-HQ, HQ));
    u[0]=cadd(e0,o0); u[4]=csub(e0,o0);
    u[1]=cadd(e1,t1); u[5]=csub(e1,t1);
    u[2]=cadd(e2,t2); u[6]=csub(e2,t2);
    u[3]=cadd(e3,t3); u[7]=csub(e3,t3);
}

__device__ __forceinline__ void twiddle15(float2 u[16], float2 w1) {
    float2 w2 = cmul(w1, w1);
    float2 w3 = cmul(w2, w1);
    float2 w4 = cmul(w2, w2);
    u[1] = cmul(u[1], w1);
    u[2] = cmul(u[2], w2);
    u[3] = cmul(u[3], w3);
    u[4] = cmul(u[4], w4);
    float2 w5 = cmul(w4, w1);  u[5] = cmul(u[5], w5);
    float2 w6 = cmul(w4, w2);  u[6] = cmul(u[6], w6);
    float2 w7 = cmul(w4, w3);  u[7] = cmul(u[7], w7);
    float2 w8 = cmul(w4, w4);  u[8] = cmul(u[8], w8);
    u[9]  = cmul(u[9],  cmul(w8, w1));
    u[10] = cmul(u[10], cmul(w8, w2));
    u[11] = cmul(u[11], cmul(w8, w3));
    u[12] = cmul(u[12], cmul(w8, w4));
    u[13] = cmul(u[13], cmul(w8, w5));
    u[14] = cmul(u[14], cmul(w8, w6));
    u[15] = cmul(u[15], cmul(w8, w7));
}

__device__ __forceinline__ void twiddle7(float2 u[8], float2 w1) {
    float2 w2 = cmul(w1, w1), w3 = cmul(w2, w1), w4 = cmul(w2, w2);
    u[1] = cmul(u[1], w1); u[2] = cmul(u[2], w2); u[3] = cmul(u[3], w3);
    u[4] = cmul(u[4], w4);
    u[5] = cmul(u[5], cmul(w4, w1));
    u[6] = cmul(u[6], cmul(w4, w2));
    u[7] = cmul(u[7], cmul(w4, w3));
}

// 2048-pt FFT, radix 16*16*8, 128 threads, 16 regs/thread, PING-PONG buffers
// (sA, sB), 3 internal syncs. Register layout in/out: u[r] = data[lt+128*r].
// Conventions:
//  - entry sync guards caller's pending reads of sA/sB vs stage-1 sA stores
//  - after return, caller may write sA IMMEDIATELY (all sA traffic done before
//    the last internal sync); caller must sync before reusing sB.
template<int SIGN>
__device__ __forceinline__ void fft2048(float2 u[16], float2* sA, float2* sB, int lt) {
    __syncthreads();
    // stage 1: R=16, p=1 (no twiddle) -> sA
    dft16<SIGN>(u);
    #pragma unroll
    for (int c = 0; c < 16; c++) sA[P16(16*lt + c)] = u[c];
    __syncthreads();
    // stage 2: R=16, p=16 : sA -> sB
    #pragma unroll
    for (int c = 0; c < 16; c++) u[c] = sA[P16(lt + 128*c)];
    {
        float a = ((SIGN < 0) ? -TWO_PI : TWO_PI) * (float)(lt & 15) * (1.0f/256.0f);
        float sn, cs; __sincosf(a, &sn, &cs);
        twiddle15(u, make_float2(cs, sn));
    }
    dft16<SIGN>(u);
    {
        int j = ((lt >> 4) << 8) + (lt & 15);
        #pragma unroll
        for (int c = 0; c < 16; c++) sB[P16(j + 16*c)] = u[c];
    }
    __syncthreads();
    // stage 3: R=8, p=256 : sB -> regs
    #pragma unroll
    for (int c = 0; c < 16; c++) u[c] = sB[P16(lt + 128*c)];
    float2 xa[8], xb[8];
    #pragma unroll
    for (int c = 0; c < 8; c++) { xa[c] = u[2*c]; xb[c] = u[2*c+1]; }
    {
        float a = ((SIGN < 0) ? -TWO_PI : TWO_PI) * (float)lt * (1.0f/2048.0f);
        float sn, cs; __sincosf(a, &sn, &cs);
        float2 wa = make_float2(cs, sn);
        const float C1 = 0.92387953251128674f;
        const float S1 = 0.38268343236508978f;
        float2 wstep = make_float2(C1, (SIGN < 0) ? -S1 : S1);  // e^{∓i pi/8}
        float2 wb = cmul(wa, wstep);
        twiddle7(xa, wa); twiddle7(xb, wb);
    }
    dft8<SIGN>(xa); dft8<SIGN>(xb);
    #pragma unroll
    for (int c = 0; c < 8; c++) { u[2*c] = xa[c]; u[2*c+1] = xb[c]; }
}

// ---------------- kernel 1: precompute Gf (rfft), Hf, Xf (folded) -----------
__global__ void __launch_bounds__(128)
k_pre(const float* __restrict__ x, const float* __restrict__ G,
      const float* __restrict__ H) {
    extern __shared__ float2 sm[];
    float2* sA = sm;
    float2* sB = sm + SMEMC;
    const int lt = threadIdx.x;
    const int v = blockIdx.x;            // 0..63 G, 64..127 H, 128..255 x
    float2 u[16];

    if (v < CIN*COUT*RANK) {
        // ---- G: rfft half-spectrum via even/odd packing ----
        const float2* g2 = (const float2*)(G + (size_t)v * NFFT);
        #pragma unroll
        for (int r = 0; r < 16; r++) u[r] = g2[lt + 128*r];
        fft2048<-1>(u, sA, sB, lt);
        #pragma unroll
        for (int r = 0; r < 16; r++) sA[P16(lt + 128*r)] = u[r];   // safe: no sync needed
        __syncthreads();
        #pragma unroll
        for (int r = 0; r < 16; r++) {
            int m = lt + 128*r;
            int pm = (MH - m) & (MH - 1);
            float2 Zp = sA[P16(pm)];
            float2 E  = make_float2(0.5f*(u[r].x + Zp.x), 0.5f*(u[r].y - Zp.y));
            float2 Od = make_float2(0.5f*(u[r].x - Zp.x), 0.5f*(u[r].y + Zp.y));
            float2 O  = make_float2(Od.y, -Od.x);          // -i * Od
            float sn, cs; __sincosf(A2 * (float)m, &sn, &cs);
            d_Gf[v][m] = cadd(E, cmul(make_float2(cs, -sn), O));
            if (m == 0) d_GfN[v] = u[r].x - u[r].y;        // Nyquist (real)
        }
    } else if (v < 2*CIN*COUT*RANK) {
        // ---- H: folded transform of h~ = (h0, -h_{N-1}, ..., -h_1) ----
        int vv = v - CIN*COUT*RANK;
        const float* h = H + (size_t)vv * NFFT;
        #pragma unroll
        for (int r = 0; r < 16; r++) {
            int m = lt + 128*r;
            float2 bv;
            if (m == 0) {
                bv = make_float2(h[0], -h[MH]);
            } else {
                float hr = h[NFFT - m], hi = h[MH - m];
                float sn, cs; __sincosf(A1 * (float)m, &sn, &cs);
                bv = make_float2(-(hr*cs - hi*sn), -(hr*sn + hi*cs));
            }
            u[r] = bv;
        }
        fft2048<-1>(u, sA, sB, lt);
        #pragma unroll
        for (int r = 0; r < 16; r++) d_Hf[vv][lt + 128*r] = u[r];
    } else {
        // ---- x: folded transform ----
        int ib = v - 2*CIN*COUT*RANK;    // 0..127
        const float* xp = x + (size_t)ib * NFFT;
        #pragma unroll
        for (int r = 0; r < 16; r++) {
            int m = lt + 128*r;
            float xr = xp[m], xi = xp[m + MH];
            float sn, cs; __sincosf(A1 * (float)m, &sn, &cs);
            u[r] = cmul(make_float2(xr, xi), make_float2(cs, sn));
        }
        fft2048<-1>(u, sA, sB, lt);
        #pragma unroll
        for (int r = 0; r < 16; r++) d_Xf[ib][lt + 128*r] = u[r];
    }
}

// ---------------- kernel 2: main — one CTA per (jb, i); accumulate over s ---
__global__ void __launch_bounds__(128, 4)
k_main() {
    extern __shared__ float2 sm[];
    float2* sA  = sm;
    float2* sB  = sm + SMEMC;
    float2* sXf = sm + 2*SMEMC;          // 2048 unpadded slots
    const int lt = threadIdx.x;
    const int jb = blockIdx.x;           // j*BATCH + b
    const int i  = blockIdx.y;           // cin
    const int j  = jb >> 5;              // BATCH = 32
    const int b  = jb & 31;

    // cache X^ once (reused by all 4 s-iterations)
    #pragma unroll
    for (int r = 0; r < 16; r++) {
        int m = lt + 128*r;
        sXf[m] = __ldg(&d_Xf[i * BATCH + b][m]);
    }
    // no explicit sync: each thread reads back only slots it wrote? NO —
    // T^ multiply reads same slots it wrote (m = lt+128r), so per-thread
    // consistency suffices for iteration 0; still sync for cross-warp safety
    __syncthreads();

    float2 acc[16];
    #pragma unroll
    for (int r = 0; r < 16; r++) acc[r] = make_float2(0.0f, 0.0f);
    float accN = 0.0f;

    #pragma unroll 1
    for (int s = 0; s < RANK; s++) {
        const int v = (i * COUT + j) * RANK + s;
        const float2* __restrict__ Hf = d_Hf[v];
        const float2* __restrict__ Gf = d_Gf[v];
        float2 u[16];
        // T^ = H^ * X^
        #pragma unroll
        for (int r = 0; r < 16; r++) {
            int m = lt + 128*r;
            u[r] = cmul(__ldg(&Hf[m]), sXf[m]);
        }
        // c = IFFTu(T^)
        fft2048<1>(u, sA, sB, lt);
        // unpack: t_k = Re(e1bar*c)/M, t_{k+M} = Im(...)/M  -> sA (safe now)
        float* sT = (float*)sA;
        #pragma unroll
        for (int r = 0; r < 16; r++) {
            int m = lt + 128*r;
            float sn, cs; __sincosf(A1 * (float)m, &sn, &cs);
            float2 ce = cmul(u[r], make_float2(cs, -sn));
            sT[m]      = ce.x * INV_M;
            sT[m + MH] = ce.y * INV_M;
        }
        __syncthreads();
        // repack for cyclic rfft: z_m = t_{2m} + i t_{2m+1}
        #pragma unroll
        for (int r = 0; r < 16; r++) u[r] = ((float2*)sT)[lt + 128*r];
        fft2048<-1>(u, sA, sB, lt);
        // partner exchange (sA safe immediately) + Hermitian unfold + Gf mult
        #pragma unroll
        for (int r = 0; r < 16; r++) sA[P16(lt + 128*r)] = u[r];
        __syncthreads();
        #pragma unroll
        for (int r = 0; r < 16; r++) {
            int m = lt + 128*r;
            int pm = (MH - m) & (MH - 1);
            float2 Zp = sA[P16(pm)];
            float2 E  = make_float2(0.5f*(u[r].x + Zp.x), 0.5f*(u[r].y - Zp.y));
            float2 Od = make_float2(0.5f*(u[r].x - Zp.x), 0.5f*(u[r].y + Zp.y));
            float2 O  = make_float2(Od.y, -Od.x);
            float sn, cs; __sincosf(A2 * (float)m, &sn, &cs);
            float2 Tf = cadd(E, cmul(make_float2(cs, -sn), O));
            acc[r] = cadd(acc[r], cmul(__ldg(&Gf[m]), Tf));
            if (m == 0)
                accN = fmaf(d_GfN[v], u[r].x - u[r].y, accN);
        }
    }
    float2* __restrict__ dst = d_Yp[i][jb];
    #pragma unroll
    for (int r = 0; r < 16; r++) dst[lt + 128*r] = acc[r];
    if (lt == 0) d_YpN[i][jb] = accN;
}

// ---------------- kernel 3: sum partials, inverse rfft, real output ---------
__global__ void __launch_bounds__(128)
k_final(float* __restrict__ out) {
    extern __shared__ float2 sm[];
    float2* sA = sm;
    float2* sB = sm + SMEMC;
    const int lt = threadIdx.x;
    const int jb = blockIdx.x;           // 0..127

    float2 u[16];
    float SN = 0.0f;
    #pragma unroll
    for (int r = 0; r < 16; r++) {
        int m = lt + 128*r;
        float2 S = cadd(cadd(__ldg(&d_Yp[0][jb][m]), __ldg(&d_Yp[1][jb][m])),
                        cadd(__ldg(&d_Yp[2][jb][m]), __ldg(&d_Yp[3][jb][m])));
        sA[P16(m)] = S;
        u[r] = S;
    }
    if (lt == 0)
        SN = d_YpN[0][jb] + d_YpN[1][jb] + d_YpN[2][jb] + d_YpN[3][jb];
    __syncthreads();
    #pragma unroll
    for (int r = 0; r < 16; r++) {
        int m = lt + 128*r;
        int pm = (MH - m) & (MH - 1);
        float2 P = (m == 0) ? make_float2(SN, 0.0f) : sA[P16(pm)];
        float2 E    = make_float2(0.5f*(u[r].x + P.x), 0.5f*(u[r].y - P.y));
        float2 diff = make_float2(0.5f*(u[r].x - P.x), 0.5f*(u[r].y + P.y));
        float sn, cs; __sincosf(A2 * (float)m, &sn, &cs);
        float2 O = cmul(make_float2(cs, sn), diff);        // e^{+i pi m/2048} * diff
        u[r] = make_float2(E.x - O.y, E.y + O.x);          // Z = E + iO
    }
    fft2048<1>(u, sA, sB, lt);
    float2* outp = (float2*)(out + (size_t)jb * NFFT);
    #pragma unroll
    for (int r = 0; r < 16; r++) {
        int m = lt + 128*r;
        outp[m] = make_float2(u[r].x * INV_M, u[r].y * INV_M);
    }
}

// ---------------- launch ----------------------------------------------------
extern "C" void kernel_launch(void* const* d_in, const int* in_sizes, int n_in,
                              void* d_out, int out_size) {
    const float* x = (const float*)d_in[0];   // (CIN, B, N)
    const float* G = (const float*)d_in[1];   // (CIN, COUT, R, N)
    const float* H = (const float*)d_in[2];   // (CIN, COUT, R, N)
    float* out = (float*)d_out;               // (COUT, B, N) fp32

    const int shmem2 = 2 * SMEMC * (int)sizeof(float2);          // 34816
    const int shmemM = (2 * SMEMC + MH) * (int)sizeof(float2);   // 51200
    cudaFuncSetAttribute(k_pre,   cudaFuncAttributeMaxDynamicSharedMemorySize, shmem2);
    cudaFuncSetAttribute(k_main,  cudaFuncAttributeMaxDynamicSharedMemorySize, shmemM);
    cudaFuncSetAttribute(k_final, cudaFuncAttributeMaxDynamicSharedMemorySize, shmem2);

    k_pre<<<2 * CIN * COUT * RANK + CIN * BATCH, 128, shmem2>>>(x, G, H);
    k_main<<<dim3(COUT * BATCH, CIN), 128, shmemM>>>();
    k_final<<<COUT * BATCH, 128, shmem2>>>(out);
}